// round 2
// baseline (speedup 1.0000x reference)
#include <cuda_runtime.h>
#include <cuda_bf16.h>
#include <math_constants.h>

// Problem constants (from reference): T=2048, N=64, D=1024
#define T_DIM 2048
#define N_DIM 64
#define D_DIM 1024
#define D_VEC (D_DIM / 4)          // 256 float4 per row
#define VEC_PER_LANE 8             // 256 / 32 lanes
#define T_PER_BLOCK 64             // gridDim.x = T/T_PER_BLOCK = 32
#define WARPS_PER_BLOCK 8
#define HALF_LOG_2PI 0.91893853320467274178f
#define EPS_VAR 1e-6f

__global__ void zero_out_kernel(float* __restrict__ out) {
    if (threadIdx.x < N_DIM) out[threadIdx.x] = 0.0f;
}

__global__ __launch_bounds__(WARPS_PER_BLOCK * 32)
void gnll_kernel(const float* __restrict__ y,     // (T, N)
                 const float4* __restrict__ x4,   // (T, N, D/4)
                 const float4* __restrict__ W4,   // (2, D/4)
                 const int* __restrict__ lens,    // (N,)
                 float* __restrict__ out)         // (N,)
{
    const int n    = blockIdx.y;
    const int len  = lens[n];
    const int t0   = blockIdx.x * T_PER_BLOCK;
    const int wid  = threadIdx.x >> 5;
    const int lane = threadIdx.x & 31;

    __shared__ float s_partial[WARPS_PER_BLOCK];

    float warp_sum = 0.0f;

    if (t0 < len) {
        // Preload W lane-striped into registers, matching the x access pattern.
        float4 w0[VEC_PER_LANE], w1[VEC_PER_LANE];
        #pragma unroll
        for (int i = 0; i < VEC_PER_LANE; i++) {
            w0[i] = W4[i * 32 + lane];
            w1[i] = W4[D_VEC + i * 32 + lane];
        }

        const int t_end = min(t0 + T_PER_BLOCK, len);
        for (int t = t0 + wid; t < t_end; t += WARPS_PER_BLOCK) {
            const float4* row = x4 + ((size_t)t * N_DIM + n) * D_VEC;
            float a0 = 0.0f, a1 = 0.0f;
            #pragma unroll
            for (int i = 0; i < VEC_PER_LANE; i++) {
                float4 v = row[i * 32 + lane];
                a0 = fmaf(v.x, w0[i].x, a0);
                a0 = fmaf(v.y, w0[i].y, a0);
                a0 = fmaf(v.z, w0[i].z, a0);
                a0 = fmaf(v.w, w0[i].w, a0);
                a1 = fmaf(v.x, w1[i].x, a1);
                a1 = fmaf(v.y, w1[i].y, a1);
                a1 = fmaf(v.z, w1[i].z, a1);
                a1 = fmaf(v.w, w1[i].w, a1);
            }
            // warp tree-reduce both accumulators
            #pragma unroll
            for (int off = 16; off > 0; off >>= 1) {
                a0 += __shfl_xor_sync(0xFFFFFFFFu, a0, off);
                a1 += __shfl_xor_sync(0xFFFFFFFFu, a1, off);
            }
            if (lane == 0) {
                float mu  = a0;
                float var = 1.0f / (1.0f + expf(-a1));   // sigmoid
                var = fmaxf(var, EPS_VAR);
                float d = y[t * N_DIM + n] - mu;
                warp_sum += 0.5f * (logf(var) + d * d / var) + HALF_LOG_2PI;
            }
        }
    }

    if (lane == 0) s_partial[wid] = warp_sum;
    __syncthreads();
    if (threadIdx.x == 0) {
        float s = 0.0f;
        #pragma unroll
        for (int i = 0; i < WARPS_PER_BLOCK; i++) s += s_partial[i];
        if (s != 0.0f || blockIdx.x == 0)
            atomicAdd(&out[n], s);
        // note: blocks fully past len contribute exactly 0; atomic skipped.
    }
}

extern "C" void kernel_launch(void* const* d_in, const int* in_sizes, int n_in,
                              void* d_out, int out_size) {
    // metadata order: y (T*N f32), x (T*N*D f32), W (2*D f32), lens (N i32)
    const float*  y    = (const float*)d_in[0];
    const float4* x4   = (const float4*)d_in[1];
    const float4* W4   = (const float4*)d_in[2];
    const int*    lens = (const int*)d_in[3];
    float*        out  = (float*)d_out;

    zero_out_kernel<<<1, 64>>>(out);

    dim3 grid(T_DIM / T_PER_BLOCK, N_DIM);
    dim3 block(WARPS_PER_BLOCK * 32);
    gnll_kernel<<<grid, block>>>(y, x4, W4, lens, out);
}